// round 13
// baseline (speedup 1.0000x reference)
#include <cuda_runtime.h>
#include <cuda_fp16.h>
#include <cstdint>

// ===========================================================================
// TernaryLinear: out[8192,11008] = x[8192,4096] @ sign(W)[11008,4096]^T + bias
//
// R13: R9 chassis (best: 1699.8us, tensor 81.7%) with ONE isolated change:
// two BK=32 stages processed per cp_wait+__syncthreads -> 64 syncs instead of
// 128. Loader (sector-perfect 4x64B), 80B rows, warp layout, frag math all
// byte-identical to R9. NSTAGES=6 (184,320B smem).
// R12's occ-2 attempt regressed (+6.4%): same 8 warps/SM but 2x B traffic.
// ===========================================================================

#define DEVFN __device__ __forceinline__

static constexpr int Mdim = 8192, Ndim = 11008, Kdim = 4096;
static constexpr int BM = 128, BN = 256;
static constexpr int STRIDE = 80;                 // 64B K-chunk + 16B pad
static constexpr int NSTAGES = 6;
static constexpr int A_BYTES = BM * STRIDE;       // 10240
static constexpr int B_BYTES = BN * STRIDE;       // 20480
static constexpr int STAGE = A_BYTES + B_BYTES;   // 30720
static constexpr int SMEM_TOTAL = NSTAGES * STAGE;// 184320
static constexpr int KCHUNKS = (Kdim * 2) / 64;   // 128 BK=32 chunks
static constexpr int KITER2 = KCHUNKS / 2;        // 64 double-chunk iterations

static constexpr int MTILES = Mdim / BM;          // 64
static constexpr int NTILES = Ndim / BN;          // 43
static constexpr int GROUP_M = 16;

// -------------------- scratch (device globals; no cudaMalloc) --------------
__device__ __align__(128) unsigned char g_xh[(size_t)Mdim * Kdim * 2];
__device__ __align__(128) unsigned char g_wh[(size_t)Ndim * Kdim * 2];

// -------------------- PTX helpers ------------------------------------------
DEVFN uint32_t smem_u32(const void* p) {
    uint32_t a;
    asm("{ .reg .u64 t; cvta.to.shared.u64 t, %1; cvt.u32.u64 %0, t; }"
        : "=r"(a) : "l"(p));
    return a;
}
DEVFN void cp16(uint32_t dst, const void* src) {
    asm volatile("cp.async.cg.shared.global [%0], [%1], 16;"
                 :: "r"(dst), "l"(src) : "memory");
}
DEVFN void cp_commit() { asm volatile("cp.async.commit_group;" ::: "memory"); }
template <int N> DEVFN void cp_wait() {
    asm volatile("cp.async.wait_group %0;" :: "n"(N) : "memory");
}
DEVFN void ldsm4(uint32_t* r, uint32_t addr) {
    asm volatile("ldmatrix.sync.aligned.m8n8.x4.shared.b16 {%0,%1,%2,%3}, [%4];"
                 : "=r"(r[0]), "=r"(r[1]), "=r"(r[2]), "=r"(r[3]) : "r"(addr));
}
DEVFN void mma16816(float* d, const uint32_t* a, uint32_t b0, uint32_t b1) {
    asm volatile(
        "mma.sync.aligned.m16n8k16.row.col.f32.f16.f16.f32 "
        "{%0,%1,%2,%3}, {%4,%5,%6,%7}, {%8,%9}, {%0,%1,%2,%3};"
        : "+f"(d[0]), "+f"(d[1]), "+f"(d[2]), "+f"(d[3])
        : "r"(a[0]), "r"(a[1]), "r"(a[2]), "r"(a[3]), "r"(b0), "r"(b1));
}

// -------------------- fused preprocessing ----------------------------------
static constexpr int XBLK = (Mdim * Kdim / 4) / 256;   // 32768
static constexpr int WBLK = (Ndim * Kdim / 4) / 256;   // 44032

__global__ void prep_fused(const float4* __restrict__ x,
                           const float4* __restrict__ w,
                           uint2* __restrict__ xh, uint2* __restrict__ wh) {
    int b = blockIdx.x;
    if (b < XBLK) {
        int i = b * 256 + threadIdx.x;
        float4 v = x[i];
        __half2 h0 = __floats2half2_rn(v.x, v.y);
        __half2 h1 = __floats2half2_rn(v.z, v.w);
        uint2 u;
        u.x = *reinterpret_cast<uint32_t*>(&h0);
        u.y = *reinterpret_cast<uint32_t*>(&h1);
        xh[i] = u;
    } else {
        int i = (b - XBLK) * 256 + threadIdx.x;
        float4 v = w[i];
        float f[4] = {v.x, v.y, v.z, v.w};
        uint32_t s[4];
#pragma unroll
        for (int j = 0; j < 4; ++j)
            s[j] = f[j] > 0.f ? 0x3C00u : (f[j] < 0.f ? 0xBC00u : 0u);
        uint2 u;
        u.x = s[0] | (s[1] << 16);
        u.y = s[2] | (s[3] << 16);
        wh[i] = u;
    }
}

// -------------------- GEMM kernel ------------------------------------------
__global__ void __launch_bounds__(256, 1) gemm_f16(
    const unsigned char* __restrict__ A,   // fp16 [M][K]
    const unsigned char* __restrict__ B,   // fp16 [N][K]
    const float* __restrict__ bias,
    float* __restrict__ out)
{
    extern __shared__ __align__(128) unsigned char smem[];
    const uint32_t sbase = smem_u32(smem);
    const int tid = threadIdx.x;
    const int lane = tid & 31;
    const int wid = tid >> 5;
    const int wm = wid >> 2;        // 0..1
    const int wn = wid & 3;         // 0..3

    // ---- L2-friendly raster: bands of GROUP_M M-tiles sweeping N ----
    const int bid = blockIdx.y * gridDim.x + blockIdx.x;
    const int band = bid / (GROUP_M * NTILES);
    const int rem = bid % (GROUP_M * NTILES);
    const int m0 = (band * GROUP_M + (rem % GROUP_M)) * BM;
    const int n0 = (rem / GROUP_M) * BN;

    // ---- cp.async addressing: 4 lanes x 64B contiguous per row ----
    const int ar = tid >> 2;             // 0..63
    const int ac = (tid & 3) * 16;
    const size_t rowbytes = (size_t)Kdim * 2;   // 8192
    const unsigned char* gA = A + (size_t)(m0 + ar) * rowbytes + ac;
    const unsigned char* gB = B + (size_t)(n0 + ar) * rowbytes + ac;
    const uint32_t sA = sbase + ar * STRIDE + ac;
    const uint32_t sB = sbase + A_BYTES + ar * STRIDE + ac;

    // ---- ldmatrix per-lane addresses ----
    uint32_t aAddr[4], bAddr[4];
    {
        int arow = wm * 64 + (lane & 15);
        int acol = (lane & 16);
        int brow = wn * 64 + ((lane >> 4) << 3) + (lane & 7);
        int bcol = (lane & 8) << 1;
#pragma unroll
        for (int f = 0; f < 4; ++f) {
            aAddr[f] = sbase + (arow + f * 16) * STRIDE + acol;
            bAddr[f] = sbase + A_BYTES + (brow + f * 16) * STRIDE + bcol;
        }
    }

    float acc[4][8][4];
#pragma unroll
    for (int i = 0; i < 4; ++i)
#pragma unroll
        for (int j = 0; j < 8; ++j)
#pragma unroll
            for (int k = 0; k < 4; ++k) acc[i][j][k] = 0.f;

    auto load_stage = [&](int it, int s) {
        const uint32_t so = (uint32_t)s * STAGE;
        const size_t ko = (size_t)it * 64;
        cp16(sA + so, gA + ko);
        cp16(sA + so + 64 * STRIDE, gA + ko + 64 * rowbytes);
#pragma unroll
        for (int j = 0; j < 4; ++j)
            cp16(sB + so + j * 64 * STRIDE, gB + ko + (size_t)j * 64 * rowbytes);
    };

    auto mma_all = [&](uint32_t af[4][4], uint32_t bf[4][4]) {
#pragma unroll
        for (int f = 0; f < 4; ++f)
#pragma unroll
            for (int p = 0; p < 4; ++p) {
                mma16816(acc[f][2 * p], af[f], bf[p][0], bf[p][1]);
                mma16816(acc[f][2 * p + 1], af[f], bf[p][2], bf[p][3]);
            }
    };

    // ---- prologue: issue 5 stages; wait<2> -> stages 0,1,2 resident ----
#pragma unroll
    for (int s = 0; s < NSTAGES - 1; ++s) {
        load_stage(s, s);
        cp_commit();
    }
    cp_wait<2>();
    __syncthreads();

    // frag double buffers; hold chunk-0 k0 frags
    uint32_t afr[2][4][4], bfr[2][4][4];
#pragma unroll
    for (int f = 0; f < 4; ++f) ldsm4(afr[0][f], aAddr[f]);
#pragma unroll
    for (int p = 0; p < 4; ++p) ldsm4(bfr[0][p], bAddr[p]);

    int cur = 0;
    for (int i2 = 0; i2 < KITER2; ++i2) {
        const int c0 = 2 * i2;
        const uint32_t off0 = (uint32_t)(c0 % NSTAGES) * STAGE;
        const uint32_t off1 = (uint32_t)((c0 + 1) % NSTAGES) * STAGE;

        // c0 ks0: prefetch c0 ks1; mma
#pragma unroll
        for (int f = 0; f < 4; ++f) ldsm4(afr[cur ^ 1][f], aAddr[f] + off0 + 32);
#pragma unroll
        for (int p = 0; p < 4; ++p) ldsm4(bfr[cur ^ 1][p], bAddr[p] + off0 + 32);
        mma_all(afr[cur], bfr[cur]); cur ^= 1;

        // c0 ks1: prefetch c1 ks0 (c1 resident via prev iter's wait); mma
#pragma unroll
        for (int f = 0; f < 4; ++f) ldsm4(afr[cur ^ 1][f], aAddr[f] + off1);
#pragma unroll
        for (int p = 0; p < 4; ++p) ldsm4(bfr[cur ^ 1][p], bAddr[p] + off1);
        mma_all(afr[cur], bfr[cur]); cur ^= 1;

        // c1 ks0: prefetch c1 ks1; mma
#pragma unroll
        for (int f = 0; f < 4; ++f) ldsm4(afr[cur ^ 1][f], aAddr[f] + off1 + 32);
#pragma unroll
        for (int p = 0; p < 4; ++p) ldsm4(bfr[cur ^ 1][p], bAddr[p] + off1 + 32);
        mma_all(afr[cur], bfr[cur]); cur ^= 1;

        // c1 ks1: mma only
        mma_all(afr[cur], bfr[cur]);

        // ONE wait+sync per 2 chunks. Commits so far = 5 + 2*i2; wait<2> ->
        // >= 3+2*i2 groups complete -> stages 0..2*i2+2 resident.
        cp_wait<2>();
        __syncthreads();

        // prefetch c2 k0 frags (stage 2*i2+2, resident per wait above)
        if (i2 + 1 < KITER2) {
            const uint32_t off2 = (uint32_t)((c0 + 2) % NSTAGES) * STAGE;
#pragma unroll
            for (int f = 0; f < 4; ++f) ldsm4(afr[cur ^ 1][f], aAddr[f] + off2);
#pragma unroll
            for (int p = 0; p < 4; ++p) ldsm4(bfr[cur ^ 1][p], bAddr[p] + off2);
            cur ^= 1;
        }

        // refill two slots: stage 2*i2+5 (slot of stage 2*i2-1, read 1 sync
        // ago) and 2*i2+6 (slot of stage 2*i2, read before this sync).
        // Unconditional commits keep group==stage counting exact.
        const int s1 = c0 + NSTAGES - 1, s2 = c0 + NSTAGES;
        if (s1 < KCHUNKS) load_stage(s1, s1 % NSTAGES);
        cp_commit();
        if (s2 < KCHUNKS) load_stage(s2, s2 % NSTAGES);
        cp_commit();
    }

    // ---- epilogue: +bias, write float2 ----
    const int r0 = m0 + wm * 64 + (lane >> 2);
    const int c0e = n0 + wn * 64 + (lane & 3) * 2;
#pragma unroll
    for (int f = 0; f < 4; ++f) {
#pragma unroll
        for (int g = 0; g < 8; ++g) {
            int row = r0 + f * 16;
            int col = c0e + g * 8;
            float2 bz = *reinterpret_cast<const float2*>(bias + col);
            float2 o01, o23;
            o01.x = acc[f][g][0] + bz.x;
            o01.y = acc[f][g][1] + bz.y;
            o23.x = acc[f][g][2] + bz.x;
            o23.y = acc[f][g][3] + bz.y;
            *reinterpret_cast<float2*>(out + (size_t)row * Ndim + col) = o01;
            *reinterpret_cast<float2*>(out + (size_t)(row + 8) * Ndim + col) = o23;
        }
    }
}

// -------------------- host side --------------------------------------------
extern "C" void kernel_launch(void* const* d_in, const int* in_sizes, int n_in,
                              void* d_out, int out_size) {
    const float* x = (const float*)d_in[0];
    const float* w = (const float*)d_in[1];
    const float* bias = (const float*)d_in[2];
    float* out = (float*)d_out;

    void *p_xh = nullptr, *p_wh = nullptr;
    cudaGetSymbolAddress(&p_xh, g_xh);
    cudaGetSymbolAddress(&p_wh, g_wh);

    prep_fused<<<XBLK + WBLK, 256>>>((const float4*)x, (const float4*)w,
                                     (uint2*)p_xh, (uint2*)p_wh);

    static bool attr_set = false;
    if (!attr_set) {
        cudaFuncSetAttribute(gemm_f16,
                             cudaFuncAttributeMaxDynamicSharedMemorySize,
                             SMEM_TOTAL);
        attr_set = true;
    }

    dim3 grid(NTILES, MTILES);   // 2752 CTAs, rasterized in-kernel
    gemm_f16<<<grid, 256, SMEM_TOTAL>>>(
        (const unsigned char*)p_xh, (const unsigned char*)p_wh, bias, out);
}

// round 15
// speedup vs baseline: 2.0375x; 2.0375x over previous
#include <cuda_runtime.h>
#include <cuda_fp16.h>
#include <cstdint>

// ===========================================================================
// TernaryLinear: out[8192,11008] = x[8192,4096] @ sign(W)[11008,4096]^T + bias
//
// R15: identical to R14 (broker-side container failure; audit clean).
// R9 chassis (best: 1699.8us, tensor 81.7%) with mainloop body UNCHANGED
// (one BK=32 chunk/iter; larger bodies spill: R7/R8/R13 -> 4.4ms). Single
// isolated change: wait+sync+refill only on odd iterations (64 syncs vs 128),
// two-stage refill split around the sync for slot-reuse safety.
// NSTAGES=7, smem 215040, #pragma unroll 1 protects register allocation.
// ===========================================================================

#define DEVFN __device__ __forceinline__

static constexpr int Mdim = 8192, Ndim = 11008, Kdim = 4096;
static constexpr int BM = 128, BN = 256;
static constexpr int STRIDE = 80;                 // 64B K-chunk + 16B pad
static constexpr int NSTAGES = 7;
static constexpr int A_BYTES = BM * STRIDE;       // 10240
static constexpr int B_BYTES = BN * STRIDE;       // 20480
static constexpr int STAGE = A_BYTES + B_BYTES;   // 30720
static constexpr int SMEM_TOTAL = NSTAGES * STAGE;// 215040
static constexpr int KITERS = (Kdim * 2) / 64;    // 128 BK=32 chunks

static constexpr int MTILES = Mdim / BM;          // 64
static constexpr int NTILES = Ndim / BN;          // 43
static constexpr int GROUP_M = 16;

// -------------------- scratch (device globals; no cudaMalloc) --------------
__device__ __align__(128) unsigned char g_xh[(size_t)Mdim * Kdim * 2];
__device__ __align__(128) unsigned char g_wh[(size_t)Ndim * Kdim * 2];

// -------------------- PTX helpers ------------------------------------------
DEVFN uint32_t smem_u32(const void* p) {
    uint32_t a;
    asm("{ .reg .u64 t; cvta.to.shared.u64 t, %1; cvt.u32.u64 %0, t; }"
        : "=r"(a) : "l"(p));
    return a;
}
DEVFN void cp16(uint32_t dst, const void* src) {
    asm volatile("cp.async.cg.shared.global [%0], [%1], 16;"
                 :: "r"(dst), "l"(src) : "memory");
}
DEVFN void cp_commit() { asm volatile("cp.async.commit_group;" ::: "memory"); }
template <int N> DEVFN void cp_wait() {
    asm volatile("cp.async.wait_group %0;" :: "n"(N) : "memory");
}
DEVFN void ldsm4(uint32_t* r, uint32_t addr) {
    asm volatile("ldmatrix.sync.aligned.m8n8.x4.shared.b16 {%0,%1,%2,%3}, [%4];"
                 : "=r"(r[0]), "=r"(r[1]), "=r"(r[2]), "=r"(r[3]) : "r"(addr));
}
DEVFN void mma16816(float* d, const uint32_t* a, uint32_t b0, uint32_t b1) {
    asm volatile(
        "mma.sync.aligned.m16n8k16.row.col.f32.f16.f16.f32 "
        "{%0,%1,%2,%3}, {%4,%5,%6,%7}, {%8,%9}, {%0,%1,%2,%3};"
        : "+f"(d[0]), "+f"(d[1]), "+f"(d[2]), "+f"(d[3])
        : "r"(a[0]), "r"(a[1]), "r"(a[2]), "r"(a[3]), "r"(b0), "r"(b1));
}

// -------------------- fused preprocessing ----------------------------------
static constexpr int XBLK = (Mdim * Kdim / 4) / 256;   // 32768
static constexpr int WBLK = (Ndim * Kdim / 4) / 256;   // 44032

__global__ void prep_fused(const float4* __restrict__ x,
                           const float4* __restrict__ w,
                           uint2* __restrict__ xh, uint2* __restrict__ wh) {
    int b = blockIdx.x;
    if (b < XBLK) {
        int i = b * 256 + threadIdx.x;
        float4 v = x[i];
        __half2 h0 = __floats2half2_rn(v.x, v.y);
        __half2 h1 = __floats2half2_rn(v.z, v.w);
        uint2 u;
        u.x = *reinterpret_cast<uint32_t*>(&h0);
        u.y = *reinterpret_cast<uint32_t*>(&h1);
        xh[i] = u;
    } else {
        int i = (b - XBLK) * 256 + threadIdx.x;
        float4 v = w[i];
        float f[4] = {v.x, v.y, v.z, v.w};
        uint32_t s[4];
#pragma unroll
        for (int j = 0; j < 4; ++j)
            s[j] = f[j] > 0.f ? 0x3C00u : (f[j] < 0.f ? 0xBC00u : 0u);
        uint2 u;
        u.x = s[0] | (s[1] << 16);
        u.y = s[2] | (s[3] << 16);
        wh[i] = u;
    }
}

// -------------------- GEMM kernel ------------------------------------------
__global__ void __launch_bounds__(256, 1) gemm_f16(
    const unsigned char* __restrict__ A,   // fp16 [M][K]
    const unsigned char* __restrict__ B,   // fp16 [N][K]
    const float* __restrict__ bias,
    float* __restrict__ out)
{
    extern __shared__ __align__(128) unsigned char smem[];
    const uint32_t sbase = smem_u32(smem);
    const int tid = threadIdx.x;
    const int lane = tid & 31;
    const int wid = tid >> 5;
    const int wm = wid >> 2;        // 0..1
    const int wn = wid & 3;         // 0..3

    // ---- L2-friendly raster: bands of GROUP_M M-tiles sweeping N ----
    const int bid = blockIdx.y * gridDim.x + blockIdx.x;
    const int band = bid / (GROUP_M * NTILES);
    const int rem = bid % (GROUP_M * NTILES);
    const int m0 = (band * GROUP_M + (rem % GROUP_M)) * BM;
    const int n0 = (rem / GROUP_M) * BN;

    // ---- cp.async addressing: 4 lanes x 64B contiguous per row ----
    const int ar = tid >> 2;             // 0..63
    const int ac = (tid & 3) * 16;
    const size_t rowbytes = (size_t)Kdim * 2;   // 8192
    const unsigned char* gA = A + (size_t)(m0 + ar) * rowbytes + ac;
    const unsigned char* gB = B + (size_t)(n0 + ar) * rowbytes + ac;
    const uint32_t sA = sbase + ar * STRIDE + ac;
    const uint32_t sB = sbase + A_BYTES + ar * STRIDE + ac;

    // ---- ldmatrix per-lane addresses ----
    uint32_t aAddr[4], bAddr[4];
    {
        int arow = wm * 64 + (lane & 15);
        int acol = (lane & 16);
        int brow = wn * 64 + ((lane >> 4) << 3) + (lane & 7);
        int bcol = (lane & 8) << 1;
#pragma unroll
        for (int f = 0; f < 4; ++f) {
            aAddr[f] = sbase + (arow + f * 16) * STRIDE + acol;
            bAddr[f] = sbase + A_BYTES + (brow + f * 16) * STRIDE + bcol;
        }
    }

    float acc[4][8][4];
#pragma unroll
    for (int i = 0; i < 4; ++i)
#pragma unroll
        for (int j = 0; j < 8; ++j)
#pragma unroll
            for (int k = 0; k < 4; ++k) acc[i][j][k] = 0.f;

    auto load_stage = [&](int it, int s) {
        const uint32_t so = (uint32_t)s * STAGE;
        const size_t ko = (size_t)it * 64;
        cp16(sA + so, gA + ko);
        cp16(sA + so + 64 * STRIDE, gA + ko + 64 * rowbytes);
#pragma unroll
        for (int j = 0; j < 4; ++j)
            cp16(sB + so + j * 64 * STRIDE, gB + ko + (size_t)j * 64 * rowbytes);
    };

    // ---- prologue: issue stages 0..5 (slot 6 left empty); wait<2> ----
#pragma unroll
    for (int s = 0; s < NSTAGES - 1; ++s) {
        load_stage(s, s);
        cp_commit();
    }
    cp_wait<2>();                 // 4 of 6 groups complete -> stages 0..3
    __syncthreads();

    // frag double buffers
    uint32_t afr[2][4][4], bfr[2][4][4];
#pragma unroll
    for (int f = 0; f < 4; ++f) ldsm4(afr[0][f], aAddr[f]);
#pragma unroll
    for (int p = 0; p < 4; ++p) ldsm4(bfr[0][p], bAddr[p]);

    int cur = 0;
#pragma unroll 1
    for (int i = 0; i < KITERS; ++i) {
        const uint32_t soff = (uint32_t)(i % NSTAGES) * STAGE;
        const uint32_t noff = (uint32_t)((i + 1) % NSTAGES) * STAGE;

        // ks0: prefetch ks1 frags, mma on ks0 frags
#pragma unroll
        for (int f = 0; f < 4; ++f) ldsm4(afr[cur ^ 1][f], aAddr[f] + soff + 32);
#pragma unroll
        for (int p = 0; p < 4; ++p) ldsm4(bfr[cur ^ 1][p], bAddr[p] + soff + 32);
#pragma unroll
        for (int f = 0; f < 4; ++f)
#pragma unroll
            for (int p = 0; p < 4; ++p) {
                mma16816(acc[f][2 * p], afr[cur][f], bfr[cur][p][0], bfr[cur][p][1]);
                mma16816(acc[f][2 * p + 1], afr[cur][f], bfr[cur][p][2], bfr[cur][p][3]);
            }
        cur ^= 1;

        // ks1: prefetch next-stage ks0 frags, mma on ks1 frags
#pragma unroll
        for (int f = 0; f < 4; ++f) ldsm4(afr[cur ^ 1][f], aAddr[f] + noff);
#pragma unroll
        for (int p = 0; p < 4; ++p) ldsm4(bfr[cur ^ 1][p], bAddr[p] + noff);
#pragma unroll
        for (int f = 0; f < 4; ++f)
#pragma unroll
            for (int p = 0; p < 4; ++p) {
                mma16816(acc[f][2 * p], afr[cur][f], bfr[cur][p][0], bfr[cur][p][1]);
                mma16816(acc[f][2 * p + 1], afr[cur][f], bfr[cur][p][2], bfr[cur][p][3]);
            }
        cur ^= 1;

        // sync+refill every OTHER iteration (uniform branch).
        // Refill #1 (stage i+5 -> slot of stage i-2): safe pre-sync, since
        //   stage i-2's last read was iter i-2 (odd), covered by that sync.
        // wait<2>: commits = i+6 -> i+4 complete -> stages 0..i+3 visible
        //   after the barrier, covering iters i+1 (i+1,i+2) and i+2 (i+2,i+3).
        // Refill #2 (stage i+6 -> slot of stage i-1): after sync, since
        //   stage i-1's last read was iter i-1 (even, unsynced until now).
        if (i & 1) {
            const int s1 = i + NSTAGES - 2, s2 = i + NSTAGES - 1;
            if (s1 < KITERS) load_stage(s1, s1 % NSTAGES);
            cp_commit();
            cp_wait<2>();
            __syncthreads();
            if (s2 < KITERS) load_stage(s2, s2 % NSTAGES);
            cp_commit();
        }
    }

    // ---- epilogue: +bias, write float2 ----
    const int r0 = m0 + wm * 64 + (lane >> 2);
    const int c0 = n0 + wn * 64 + (lane & 3) * 2;
#pragma unroll
    for (int f = 0; f < 4; ++f) {
#pragma unroll
        for (int g = 0; g < 8; ++g) {
            int row = r0 + f * 16;
            int col = c0 + g * 8;
            float2 bz = *reinterpret_cast<const float2*>(bias + col);
            float2 o01, o23;
            o01.x = acc[f][g][0] + bz.x;
            o01.y = acc[f][g][1] + bz.y;
            o23.x = acc[f][g][2] + bz.x;
            o23.y = acc[f][g][3] + bz.y;
            *reinterpret_cast<float2*>(out + (size_t)row * Ndim + col) = o01;
            *reinterpret_cast<float2*>(out + (size_t)(row + 8) * Ndim + col) = o23;
        }
    }
}

// -------------------- host side --------------------------------------------
extern "C" void kernel_launch(void* const* d_in, const int* in_sizes, int n_in,
                              void* d_out, int out_size) {
    const float* x = (const float*)d_in[0];
    const float* w = (const float*)d_in[1];
    const float* bias = (const float*)d_in[2];
    float* out = (float*)d_out;

    void *p_xh = nullptr, *p_wh = nullptr;
    cudaGetSymbolAddress(&p_xh, g_xh);
    cudaGetSymbolAddress(&p_wh, g_wh);

    prep_fused<<<XBLK + WBLK, 256>>>((const float4*)x, (const float4*)w,
                                     (uint2*)p_xh, (uint2*)p_wh);

    static bool attr_set = false;
    if (!attr_set) {
        cudaFuncSetAttribute(gemm_f16,
                             cudaFuncAttributeMaxDynamicSharedMemorySize,
                             SMEM_TOTAL);
        attr_set = true;
    }

    dim3 grid(NTILES, MTILES);   // 2752 CTAs, rasterized in-kernel
    gemm_f16<<<grid, 256, SMEM_TOTAL>>>(
        (const unsigned char*)p_xh, (const unsigned char*)p_wh, bias, out);
}

// round 16
// speedup vs baseline: 2.5001x; 1.2271x over previous
#include <cuda_runtime.h>
#include <cuda_fp16.h>
#include <cstdint>

// ===========================================================================
// TernaryLinear: out[8192,11008] = x[8192,4096] @ sign(W)[11008,4096]^T + bias
//
// R16: R9 chassis (best: 1699.8us, tensor 81.7%) with ONE reordering:
// per-iteration stage refill hoisted ABOVE the wait+sync (legal: the slot
// being overwritten was last read before the barrier at end of iter i-1).
// Deepens prefetch by one wait-cycle and grows post-wait residency to
// stages 0..i+3. Loop body, registers, barrier count identical to R9.
// (R13/R15 showed any change to loop SHAPE -- body size or control flow --
// breaks ptxas scheduling and regresses 1.3-2.6x.)
// ===========================================================================

#define DEVFN __device__ __forceinline__

static constexpr int Mdim = 8192, Ndim = 11008, Kdim = 4096;
static constexpr int BM = 128, BN = 256;
static constexpr int STRIDE = 80;                 // 64B K-chunk + 16B pad
static constexpr int NSTAGES = 7;
static constexpr int A_BYTES = BM * STRIDE;       // 10240
static constexpr int B_BYTES = BN * STRIDE;       // 20480
static constexpr int STAGE = A_BYTES + B_BYTES;   // 30720
static constexpr int SMEM_TOTAL = NSTAGES * STAGE;// 215040
static constexpr int KITERS = (Kdim * 2) / 64;    // 128 BK=32 chunks

static constexpr int MTILES = Mdim / BM;          // 64
static constexpr int NTILES = Ndim / BN;          // 43
static constexpr int GROUP_M = 16;

// -------------------- scratch (device globals; no cudaMalloc) --------------
__device__ __align__(128) unsigned char g_xh[(size_t)Mdim * Kdim * 2];
__device__ __align__(128) unsigned char g_wh[(size_t)Ndim * Kdim * 2];

// -------------------- PTX helpers ------------------------------------------
DEVFN uint32_t smem_u32(const void* p) {
    uint32_t a;
    asm("{ .reg .u64 t; cvta.to.shared.u64 t, %1; cvt.u32.u64 %0, t; }"
        : "=r"(a) : "l"(p));
    return a;
}
DEVFN void cp16(uint32_t dst, const void* src) {
    asm volatile("cp.async.cg.shared.global [%0], [%1], 16;"
                 :: "r"(dst), "l"(src) : "memory");
}
DEVFN void cp_commit() { asm volatile("cp.async.commit_group;" ::: "memory"); }
template <int N> DEVFN void cp_wait() {
    asm volatile("cp.async.wait_group %0;" :: "n"(N) : "memory");
}
DEVFN void ldsm4(uint32_t* r, uint32_t addr) {
    asm volatile("ldmatrix.sync.aligned.m8n8.x4.shared.b16 {%0,%1,%2,%3}, [%4];"
                 : "=r"(r[0]), "=r"(r[1]), "=r"(r[2]), "=r"(r[3]) : "r"(addr));
}
DEVFN void mma16816(float* d, const uint32_t* a, uint32_t b0, uint32_t b1) {
    asm volatile(
        "mma.sync.aligned.m16n8k16.row.col.f32.f16.f16.f32 "
        "{%0,%1,%2,%3}, {%4,%5,%6,%7}, {%8,%9}, {%0,%1,%2,%3};"
        : "+f"(d[0]), "+f"(d[1]), "+f"(d[2]), "+f"(d[3])
        : "r"(a[0]), "r"(a[1]), "r"(a[2]), "r"(a[3]), "r"(b0), "r"(b1));
}

// -------------------- fused preprocessing ----------------------------------
static constexpr int XBLK = (Mdim * Kdim / 4) / 256;   // 32768
static constexpr int WBLK = (Ndim * Kdim / 4) / 256;   // 44032

__global__ void prep_fused(const float4* __restrict__ x,
                           const float4* __restrict__ w,
                           uint2* __restrict__ xh, uint2* __restrict__ wh) {
    int b = blockIdx.x;
    if (b < XBLK) {
        int i = b * 256 + threadIdx.x;
        float4 v = x[i];
        __half2 h0 = __floats2half2_rn(v.x, v.y);
        __half2 h1 = __floats2half2_rn(v.z, v.w);
        uint2 u;
        u.x = *reinterpret_cast<uint32_t*>(&h0);
        u.y = *reinterpret_cast<uint32_t*>(&h1);
        xh[i] = u;
    } else {
        int i = (b - XBLK) * 256 + threadIdx.x;
        float4 v = w[i];
        float f[4] = {v.x, v.y, v.z, v.w};
        uint32_t s[4];
#pragma unroll
        for (int j = 0; j < 4; ++j)
            s[j] = f[j] > 0.f ? 0x3C00u : (f[j] < 0.f ? 0xBC00u : 0u);
        uint2 u;
        u.x = s[0] | (s[1] << 16);
        u.y = s[2] | (s[3] << 16);
        wh[i] = u;
    }
}

// -------------------- GEMM kernel ------------------------------------------
__global__ void __launch_bounds__(256, 1) gemm_f16(
    const unsigned char* __restrict__ A,   // fp16 [M][K]
    const unsigned char* __restrict__ B,   // fp16 [N][K]
    const float* __restrict__ bias,
    float* __restrict__ out)
{
    extern __shared__ __align__(128) unsigned char smem[];
    const uint32_t sbase = smem_u32(smem);
    const int tid = threadIdx.x;
    const int lane = tid & 31;
    const int wid = tid >> 5;
    const int wm = wid >> 2;        // 0..1
    const int wn = wid & 3;         // 0..3

    // ---- L2-friendly raster: bands of GROUP_M M-tiles sweeping N ----
    const int bid = blockIdx.y * gridDim.x + blockIdx.x;
    const int band = bid / (GROUP_M * NTILES);
    const int rem = bid % (GROUP_M * NTILES);
    const int m0 = (band * GROUP_M + (rem % GROUP_M)) * BM;
    const int n0 = (rem / GROUP_M) * BN;

    // ---- cp.async addressing: 4 lanes x 64B contiguous per row ----
    const int ar = tid >> 2;             // 0..63
    const int ac = (tid & 3) * 16;
    const size_t rowbytes = (size_t)Kdim * 2;   // 8192
    const unsigned char* gA = A + (size_t)(m0 + ar) * rowbytes + ac;
    const unsigned char* gB = B + (size_t)(n0 + ar) * rowbytes + ac;
    const uint32_t sA = sbase + ar * STRIDE + ac;
    const uint32_t sB = sbase + A_BYTES + ar * STRIDE + ac;

    // ---- ldmatrix per-lane addresses ----
    uint32_t aAddr[4], bAddr[4];
    {
        int arow = wm * 64 + (lane & 15);
        int acol = (lane & 16);
        int brow = wn * 64 + ((lane >> 4) << 3) + (lane & 7);
        int bcol = (lane & 8) << 1;
#pragma unroll
        for (int f = 0; f < 4; ++f) {
            aAddr[f] = sbase + (arow + f * 16) * STRIDE + acol;
            bAddr[f] = sbase + A_BYTES + (brow + f * 16) * STRIDE + bcol;
        }
    }

    float acc[4][8][4];
#pragma unroll
    for (int i = 0; i < 4; ++i)
#pragma unroll
        for (int j = 0; j < 8; ++j)
#pragma unroll
            for (int k = 0; k < 4; ++k) acc[i][j][k] = 0.f;

    auto load_stage = [&](int it, int s) {
        const uint32_t so = (uint32_t)s * STAGE;
        const size_t ko = (size_t)it * 64;
        cp16(sA + so, gA + ko);
        cp16(sA + so + 64 * STRIDE, gA + ko + 64 * rowbytes);
#pragma unroll
        for (int j = 0; j < 4; ++j)
            cp16(sB + so + j * 64 * STRIDE, gB + ko + (size_t)j * 64 * rowbytes);
    };

    // ---- prologue: issue stages 0..5; wait<3> -> stages 0,1,2 resident ----
#pragma unroll
    for (int s = 0; s < NSTAGES - 1; ++s) {
        load_stage(s, s);
        cp_commit();
    }
    cp_wait<NSTAGES - 4>();
    __syncthreads();

    // frag double buffers
    uint32_t afr[2][4][4], bfr[2][4][4];
#pragma unroll
    for (int f = 0; f < 4; ++f) ldsm4(afr[0][f], aAddr[f]);
#pragma unroll
    for (int p = 0; p < 4; ++p) ldsm4(bfr[0][p], bAddr[p]);

    int cur = 0;
#pragma unroll 1
    for (int i = 0; i < KITERS; ++i) {
        const uint32_t soff = (uint32_t)(i % NSTAGES) * STAGE;
        const uint32_t noff = (uint32_t)((i + 1) % NSTAGES) * STAGE;

        // ks0: prefetch ks1 frags, mma on ks0 frags
#pragma unroll
        for (int f = 0; f < 4; ++f) ldsm4(afr[cur ^ 1][f], aAddr[f] + soff + 32);
#pragma unroll
        for (int p = 0; p < 4; ++p) ldsm4(bfr[cur ^ 1][p], bAddr[p] + soff + 32);
#pragma unroll
        for (int f = 0; f < 4; ++f)
#pragma unroll
            for (int p = 0; p < 4; ++p) {
                mma16816(acc[f][2 * p], afr[cur][f], bfr[cur][p][0], bfr[cur][p][1]);
                mma16816(acc[f][2 * p + 1], afr[cur][f], bfr[cur][p][2], bfr[cur][p][3]);
            }
        cur ^= 1;

        // ks1: prefetch next-stage ks0 frags, mma on ks1 frags
#pragma unroll
        for (int f = 0; f < 4; ++f) ldsm4(afr[cur ^ 1][f], aAddr[f] + noff);
#pragma unroll
        for (int p = 0; p < 4; ++p) ldsm4(bfr[cur ^ 1][p], bAddr[p] + noff);
#pragma unroll
        for (int f = 0; f < 4; ++f)
#pragma unroll
            for (int p = 0; p < 4; ++p) {
                mma16816(acc[f][2 * p], afr[cur][f], bfr[cur][p][0], bfr[cur][p][1]);
                mma16816(acc[f][2 * p + 1], afr[cur][f], bfr[cur][p][2], bfr[cur][p][3]);
            }
        cur ^= 1;

        // REFILL FIRST (hoisted above the wait -- the only change vs R9):
        // writes slot (i+6)%7 = stage i-1's slot, whose last readers (iter
        // i-1's ks0/ks1) finished before the barrier at end of iter i-1 that
        // every thread has passed. No reader of stage i-1 exists in iter i.
        if (i + NSTAGES - 1 < KITERS) load_stage(i + NSTAGES - 1, (i + NSTAGES - 1) % NSTAGES);
        cp_commit();

        // wait<3>: commits = i+7 -> i+4 groups complete -> stages 0..i+3
        // resident (one stage MORE slack than R9), covering iter i+1's
        // soff/noff (stages i+1, i+2) with margin.
        cp_wait<NSTAGES - 4>();
        __syncthreads();
    }

    // ---- epilogue: +bias, write float2 ----
    const int r0 = m0 + wm * 64 + (lane >> 2);
    const int c0 = n0 + wn * 64 + (lane & 3) * 2;
#pragma unroll
    for (int f = 0; f < 4; ++f) {
#pragma unroll
        for (int g = 0; g < 8; ++g) {
            int row = r0 + f * 16;
            int col = c0 + g * 8;
            float2 bz = *reinterpret_cast<const float2*>(bias + col);
            float2 o01, o23;
            o01.x = acc[f][g][0] + bz.x;
            o01.y = acc[f][g][1] + bz.y;
            o23.x = acc[f][g][2] + bz.x;
            o23.y = acc[f][g][3] + bz.y;
            *reinterpret_cast<float2*>(out + (size_t)row * Ndim + col) = o01;
            *reinterpret_cast<float2*>(out + (size_t)(row + 8) * Ndim + col) = o23;
        }
    }
}

// -------------------- host side --------------------------------------------
extern "C" void kernel_launch(void* const* d_in, const int* in_sizes, int n_in,
                              void* d_out, int out_size) {
    const float* x = (const float*)d_in[0];
    const float* w = (const float*)d_in[1];
    const float* bias = (const float*)d_in[2];
    float* out = (float*)d_out;

    void *p_xh = nullptr, *p_wh = nullptr;
    cudaGetSymbolAddress(&p_xh, g_xh);
    cudaGetSymbolAddress(&p_wh, g_wh);

    prep_fused<<<XBLK + WBLK, 256>>>((const float4*)x, (const float4*)w,
                                     (uint2*)p_xh, (uint2*)p_wh);

    static bool attr_set = false;
    if (!attr_set) {
        cudaFuncSetAttribute(gemm_f16,
                             cudaFuncAttributeMaxDynamicSharedMemorySize,
                             SMEM_TOTAL);
        attr_set = true;
    }

    dim3 grid(NTILES, MTILES);   // 2752 CTAs, rasterized in-kernel
    gemm_f16<<<grid, 256, SMEM_TOTAL>>>(
        (const unsigned char*)p_xh, (const unsigned char*)p_wh, bias, out);
}